// round 3
// baseline (speedup 1.0000x reference)
#include <cuda_runtime.h>

// Online Normalization forward, fused persistent kernel (v3).
// x: [B=32, H=64, W=64, C=256] channels-last, fp32.

#define AFWD 0.999f
#define EPS  1e-5f

constexpr int Bn    = 32;
constexpr int HW    = 64 * 64;      // 4096
constexpr int Cc    = 256;
constexpr int C4    = Cc / 4;       // 64 float4 per spatial position
constexpr int S     = 32;           // spatial chunks per batch
constexpr int CHUNK = HW / S;       // 128 rows per tile
constexpr int TILES = Bn * S;       // 1024
constexpr int NCTA  = 148;          // 1 CTA/SM, co-resident (barrier-safe)

// Scratch
__device__ float g_psum[TILES * Cc];
__device__ float g_psq [TILES * Cc];
__device__ float g_tsum[Bn * Cc];
__device__ float g_tsq [Bn * Cc];
__device__ unsigned long long g_bar;    // monotonic across graph replays

// Dynamic smem (floats):
//   [0     : 8192)   mu per (t,c)
//   [8192  : 16384)  rs per (t,c)
//   [16384 : 32768)  staging: pass1/stageA reduction (red_s, red_q)
//                    stage B: tsum (16384..24576), tsq (24576..32768)
constexpr int SMEM_FLOATS = 32768;      // 128 KB

__device__ __forceinline__ void grid_barrier() {
    __syncthreads();
    if (threadIdx.x == 0) {
        __threadfence();
        unsigned long long t = atomicAdd(&g_bar, 1ULL) + 1ULL;
        unsigned long long target = ((t + NCTA - 1ULL) / NCTA) * NCTA;
        while (*((volatile unsigned long long*)&g_bar) < target) { }
        __threadfence();
    }
    __syncthreads();
}

__global__ __launch_bounds__(1024, 1)
void onorm_fused(const float4* __restrict__ x4,
                 float4* __restrict__ o4,
                 const float* __restrict__ mu0,
                 const float* __restrict__ var0) {
    extern __shared__ float sm[];
    float* sm_mu = sm;
    float* sm_rs = sm + 8192;
    float* red_s = sm + 16384;         // 4096 floats (16 groups x 64 float4)
    float* red_q = sm + 20480;         // 4096 floats
    float* sm_ts = sm + 16384;         // stage-B staging (reuses red area)
    float* sm_tq = sm + 24576;

    const int tid = threadIdx.x;
    const int cta = blockIdx.x;
    const int c4  = tid & 63;          // float4 channel index
    const int g   = tid >> 6;          // 0..15 row group
    constexpr int RPT = CHUNK / 16;    // 8 rows per thread

    // ---------------- Pass 1: per-tile partial sums ----------------
    for (int tile = cta; tile < TILES; tile += NCTA) {
        const int t = tile >> 5, s = tile & 31;
        const size_t base = (size_t)(t * HW + s * CHUNK) * C4;
        const float4* p = x4 + base + (size_t)(g * RPT) * C4 + c4;

        float4 a = {0.f,0.f,0.f,0.f}, q = {0.f,0.f,0.f,0.f};
        #pragma unroll
        for (int i = 0; i < RPT; i++) {
            float4 v = p[(size_t)i * C4];
            a.x += v.x; a.y += v.y; a.z += v.z; a.w += v.w;
            q.x = fmaf(v.x, v.x, q.x); q.y = fmaf(v.y, v.y, q.y);
            q.z = fmaf(v.z, v.z, q.z); q.w = fmaf(v.w, v.w, q.w);
        }
        ((float4*)red_s)[g * 64 + c4] = a;
        ((float4*)red_q)[g * 64 + c4] = q;
        __syncthreads();
        if (tid < 64) {
            float4 sa = {0.f,0.f,0.f,0.f}, sq = {0.f,0.f,0.f,0.f};
            #pragma unroll
            for (int j = 0; j < 16; j++) {
                float4 va = ((float4*)red_s)[j * 64 + tid];
                float4 vq = ((float4*)red_q)[j * 64 + tid];
                sa.x += va.x; sa.y += va.y; sa.z += va.z; sa.w += va.w;
                sq.x += vq.x; sq.y += vq.y; sq.z += vq.z; sq.w += vq.w;
            }
            ((float4*)g_psum)[tile * 64 + tid] = sa;
            ((float4*)g_psq )[tile * 64 + tid] = sq;
        }
        __syncthreads();
    }

    grid_barrier();

    // ---------------- Stage A: reduce 32 partials -> per-(t,c) ----------------
    if (cta < Bn) {
        const int t = cta;
        // group g sums partials s=g and s=g+16
        float4 va = ((const float4*)g_psum)[(t * S + g)      * 64 + c4];
        float4 vb = ((const float4*)g_psum)[(t * S + g + 16) * 64 + c4];
        float4 qa = ((const float4*)g_psq )[(t * S + g)      * 64 + c4];
        float4 qb = ((const float4*)g_psq )[(t * S + g + 16) * 64 + c4];
        va.x += vb.x; va.y += vb.y; va.z += vb.z; va.w += vb.w;
        qa.x += qb.x; qa.y += qb.y; qa.z += qb.z; qa.w += qb.w;
        ((float4*)red_s)[g * 64 + c4] = va;
        ((float4*)red_q)[g * 64 + c4] = qa;
        __syncthreads();
        if (tid < 64) {
            float4 sa = {0.f,0.f,0.f,0.f}, sq = {0.f,0.f,0.f,0.f};
            #pragma unroll
            for (int j = 0; j < 16; j++) {
                float4 a = ((float4*)red_s)[j * 64 + tid];
                float4 q = ((float4*)red_q)[j * 64 + tid];
                sa.x += a.x; sa.y += a.y; sa.z += a.z; sa.w += a.w;
                sq.x += q.x; sq.y += q.y; sq.z += q.z; sq.w += q.w;
            }
            ((float4*)g_tsum)[t * 64 + tid] = sa;
            ((float4*)g_tsq )[t * 64 + tid] = sq;
        }
        __syncthreads();
    }

    grid_barrier();

    // ---------------- Stage B: redundant per-CTA scan into smem ----------------
    for (int i = tid; i < Bn * Cc; i += 1024) {
        sm_ts[i] = g_tsum[i];
        sm_tq[i] = g_tsq [i];
    }
    __syncthreads();
    if (tid < Cc) {
        const int c = tid;
        float mu  = mu0[c];
        float var = var0[c];
        const float inv = 1.0f / (float)HW;
        #pragma unroll
        for (int t = 0; t < Bn; t++) {
            sm_mu[t * Cc + c] = mu;
            sm_rs[t * Cc + c] = rsqrtf(var + EPS);
            const float mean = sm_ts[t * Cc + c] * inv;
            const float vart = fmaf(-mean, mean, sm_tq[t * Cc + c] * inv);
            const float d    = mean - mu;
            var = AFWD * var + (1.0f - AFWD) * vart
                + AFWD * (1.0f - AFWD) * d * d;
            mu  = fmaf(1.0f - AFWD, d, mu);
        }
    }
    __syncthreads();

    // ---------------- Pass 3: normalize ----------------
    // Reverse tile order (most-recently-cached first). Reads use .cs (last
    // use, evict-first); writes use .cs streaming so out doesn't evict x.
    const int kmax = (TILES - 1 - cta) / NCTA;
    for (int k = kmax; k >= 0; k--) {
        const int tile = cta + k * NCTA;
        const int t = tile >> 5, s = tile & 31;
        const size_t base = (size_t)(t * HW + s * CHUNK) * C4;
        const float4 m = ((const float4*)sm_mu)[t * 64 + c4];
        const float4 r = ((const float4*)sm_rs)[t * 64 + c4];
        const float4* p = x4 + base + (size_t)(g * RPT) * C4 + c4;
        float4*       o = o4 + base + (size_t)(g * RPT) * C4 + c4;
        #pragma unroll
        for (int i = RPT - 1; i >= 0; i--) {
            float4 v = __ldcs(&p[(size_t)i * C4]);
            float4 w;
            w.x = (v.x - m.x) * r.x;
            w.y = (v.y - m.y) * r.y;
            w.z = (v.z - m.z) * r.z;
            w.w = (v.w - m.w) * r.w;
            __stcs(&o[(size_t)i * C4], w);
        }
    }
}

extern "C" void kernel_launch(void* const* d_in, const int* in_sizes, int n_in,
                              void* d_out, int out_size) {
    const float* x    = (const float*)d_in[0];
    const float* mu0  = (const float*)d_in[1];
    const float* var0 = (const float*)d_in[2];
    float* out = (float*)d_out;

    static bool attr_set = false;
    if (!attr_set) {
        cudaFuncSetAttribute(onorm_fused,
                             cudaFuncAttributeMaxDynamicSharedMemorySize,
                             SMEM_FLOATS * sizeof(float));
        attr_set = true;
    }

    onorm_fused<<<NCTA, 1024, SMEM_FLOATS * sizeof(float)>>>(
        (const float4*)x, (float4*)out, mu0, var0);
}

// round 4
// speedup vs baseline: 1.2000x; 1.2000x over previous
#include <cuda_runtime.h>

// Online Normalization forward, fused persistent kernel (v4).
// x: [B=32, H=64, W=64, C=256] channels-last, fp32.
//
// 128 CTAs x 1024 threads. CTA (t*4+q) owns quarter q of batch t (1024 rows
// = 1 MB). Pass 1: sync-free register accumulation of sum/sumsq. One grid
// barrier. Every CTA redundantly scans the EMA recurrence up to its own
// batch (deterministic). Pass 3: reverse-order re-read of the same chunk
// (hits L2/L1), normalize, streaming stores.

#define AFWD 0.999f
#define EPS  1e-5f

constexpr int Bn   = 32;
constexpr int HW   = 64 * 64;       // 4096
constexpr int Cc   = 256;
constexpr int C4   = Cc / 4;        // 64
constexpr int NCTA = 128;           // 32 batches x 4 quarters
constexpr int ROWS = HW / 4;        // 1024 rows per CTA
constexpr int ITER = ROWS / 16;     // 64 rows per thread (16 row-groups)

// Scratch: 4 partials per (batch, channel)
__device__ float g_psum[Bn * 4 * Cc];
__device__ float g_psq [Bn * 4 * Cc];
__device__ unsigned long long g_bar;   // monotonic across graph replays

// smem: red_s[4096] red_q[4096] (float4-aligned), mu[256], rs[256]
constexpr int SMEM_FLOATS = 4096 + 4096 + 256 + 256;

__device__ __forceinline__ void grid_barrier() {
    __syncthreads();
    if (threadIdx.x == 0) {
        __threadfence();
        unsigned long long t = atomicAdd(&g_bar, 1ULL) + 1ULL;
        unsigned long long target = ((t + NCTA - 1ULL) / NCTA) * NCTA;
        while (*((volatile unsigned long long*)&g_bar) < target) { }
        __threadfence();
    }
    __syncthreads();
}

__global__ __launch_bounds__(1024, 1)
void onorm_fused(const float4* __restrict__ x4,
                 float4* __restrict__ o4,
                 const float* __restrict__ mu0,
                 const float* __restrict__ var0) {
    extern __shared__ float sm[];
    float* red_s = sm;                 // 4096 floats
    float* red_q = sm + 4096;          // 4096 floats
    float* sm_mu = sm + 8192;          // 256 floats (own batch only)
    float* sm_rs = sm + 8448;          // 256 floats

    const int tid = threadIdx.x;
    const int cta = blockIdx.x;
    const int c4  = tid & 63;          // float4 channel index
    const int rg  = tid >> 6;          // 0..15 row group
    const int t   = cta >> 2;          // batch owned by this CTA
    const int qq  = cta & 3;           // quarter of the batch

    const size_t base = ((size_t)t * HW + (size_t)qq * ROWS) * C4;
    const float4* p = x4 + base + (size_t)rg * C4 + c4;

    // ---------------- Pass 1: sync-free streaming accumulation ----------------
    float4 a = {0.f,0.f,0.f,0.f}, q = {0.f,0.f,0.f,0.f};
    #pragma unroll 8
    for (int i = 0; i < ITER; i++) {
        float4 v = p[(size_t)i * 16 * C4];
        a.x += v.x; a.y += v.y; a.z += v.z; a.w += v.w;
        q.x = fmaf(v.x, v.x, q.x); q.y = fmaf(v.y, v.y, q.y);
        q.z = fmaf(v.z, v.z, q.z); q.w = fmaf(v.w, v.w, q.w);
    }
    ((float4*)red_s)[rg * 64 + c4] = a;
    ((float4*)red_q)[rg * 64 + c4] = q;
    __syncthreads();
    if (tid < 64) {
        float4 sa = {0.f,0.f,0.f,0.f}, sq = {0.f,0.f,0.f,0.f};
        #pragma unroll
        for (int j = 0; j < 16; j++) {
            float4 va = ((float4*)red_s)[j * 64 + tid];
            float4 vq = ((float4*)red_q)[j * 64 + tid];
            sa.x += va.x; sa.y += va.y; sa.z += va.z; sa.w += va.w;
            sq.x += vq.x; sq.y += vq.y; sq.z += vq.z; sq.w += vq.w;
        }
        ((float4*)g_psum)[(t * 4 + qq) * 64 + tid] = sa;
        ((float4*)g_psq )[(t * 4 + qq) * 64 + tid] = sq;
    }

    grid_barrier();

    // ------------- Scan (redundant per CTA, up to own batch, from L2) ---------
    if (tid < Cc) {
        const int c = tid;
        float mu  = mu0[c];
        float var = var0[c];
        const float inv = 1.0f / (float)HW;
        for (int tt = 0; ; tt++) {
            if (tt == t) {
                sm_mu[c] = mu;
                sm_rs[c] = rsqrtf(var + EPS);
                break;
            }
            float s  = g_psum[(tt * 4 + 0) * Cc + c] + g_psum[(tt * 4 + 1) * Cc + c]
                     + g_psum[(tt * 4 + 2) * Cc + c] + g_psum[(tt * 4 + 3) * Cc + c];
            float s2 = g_psq [(tt * 4 + 0) * Cc + c] + g_psq [(tt * 4 + 1) * Cc + c]
                     + g_psq [(tt * 4 + 2) * Cc + c] + g_psq [(tt * 4 + 3) * Cc + c];
            const float mean = s * inv;
            const float vart = fmaf(-mean, mean, s2 * inv);
            const float d    = mean - mu;
            var = AFWD * var + (1.0f - AFWD) * vart
                + AFWD * (1.0f - AFWD) * d * d;
            mu  = fmaf(1.0f - AFWD, d, mu);
        }
    }
    __syncthreads();

    // ---------------- Pass 3: normalize own chunk (reverse order) -------------
    const float4 m = ((const float4*)sm_mu)[c4];
    const float4 r = ((const float4*)sm_rs)[c4];
    float4* o = o4 + base + (size_t)rg * C4 + c4;
    #pragma unroll 8
    for (int i = ITER - 1; i >= 0; i--) {
        float4 v = p[(size_t)i * 16 * C4];
        float4 w;
        w.x = (v.x - m.x) * r.x;
        w.y = (v.y - m.y) * r.y;
        w.z = (v.z - m.z) * r.z;
        w.w = (v.w - m.w) * r.w;
        __stcs(&o[(size_t)i * 16 * C4], w);
    }
}

extern "C" void kernel_launch(void* const* d_in, const int* in_sizes, int n_in,
                              void* d_out, int out_size) {
    const float* x    = (const float*)d_in[0];
    const float* mu0  = (const float*)d_in[1];
    const float* var0 = (const float*)d_in[2];
    float* out = (float*)d_out;

    onorm_fused<<<NCTA, 1024, SMEM_FLOATS * sizeof(float)>>>(
        (const float4*)x, (float4*)out, mu0, var0);
}